// round 5
// baseline (speedup 1.0000x reference)
#include <cuda_runtime.h>
#include <cuda_fp16.h>
#include <cstdint>

// ---------------- problem constants ----------------
#define PN         8
#define SEQ        4096
#define DIN        256
#define DOUT       256
#define LEVELS     7
#define TILE_M     128
#define KCH        64
#define NCHUNK     (DIN / KCH)          // 4
#define NTHREADS   256
#define M_PER_PATH 32768                // bpp * SEQ
#define M_TOTAL    (PN * M_PER_PATH)    // 262144
#define GRID       (M_TOTAL / TILE_M)   // 2048

// ---------------- device scratch (globals: no allocs) ----------------
__device__ __align__(16) __half g_w[LEVELS * DOUT * DIN];
__device__ int g_levels[PN];

// ---------------- smem layout (bytes) ----------------
#define A_OFF      0                    // 128 x 64 fp16 = 16 KB
#define B_OFF      16384                // 256 x 64 fp16 = 32 KB
#define BUF_BYTES  49152                // 48 KB per stage
#define SMEM_BYTES (2 * BUF_BYTES)      // 96 KB

#define SWZ(o) ((o) ^ (((o) >> 3) & 0x70))

// ---------------- helpers ----------------
static __device__ __forceinline__ uint32_t smem_u32(const void* p) {
    uint32_t a;
    asm("{ .reg .u64 t; cvta.to.shared.u64 t, %1; cvt.u32.u64 %0, t; }" : "=r"(a) : "l"(p));
    return a;
}

static __device__ __forceinline__ void cp16(uint32_t dst, const void* src) {
    asm volatile("cp.async.cg.shared.global [%0], [%1], 16;" :: "r"(dst), "l"(src) : "memory");
}
#define CP_COMMIT() asm volatile("cp.async.commit_group;" ::: "memory")
#define CP_WAIT0()  asm volatile("cp.async.wait_group 0;" ::: "memory")

static __device__ __forceinline__ void ldsm4(uint32_t* r, uint32_t addr) {
    asm volatile("ldmatrix.sync.aligned.m8n8.x4.shared.b16 {%0,%1,%2,%3}, [%4];"
                 : "=r"(r[0]), "=r"(r[1]), "=r"(r[2]), "=r"(r[3]) : "r"(addr));
}

static __device__ __forceinline__ void mma16816(float* d, const uint32_t* a, const uint32_t* b) {
    asm volatile(
        "mma.sync.aligned.m16n8k16.row.col.f32.f16.f16.f32 "
        "{%0,%1,%2,%3}, {%4,%5,%6,%7}, {%8,%9}, {%0,%1,%2,%3};"
        : "+f"(d[0]), "+f"(d[1]), "+f"(d[2]), "+f"(d[3])
        : "r"(a[0]), "r"(a[1]), "r"(a[2]), "r"(a[3]), "r"(b[0]), "r"(b[1]));
}

static __device__ __forceinline__ uint32_t pack_h2(float f0, float f1) {
    __half2 h = __floats2half2_rn(f0, f1);
    return *reinterpret_cast<uint32_t*>(&h);
}

// ---------------- prep pass: fp32 -> fp16 weights + assigned_bits dtype fix ----------------
// assigned_bits may be int64 OR int32 (JAX x64-disabled silently gives int32).
// Rule: if ALL 8 values under the int64 interpretation are in [0, LEVELS),
// the data really is int64; otherwise interpret as int32.
__global__ void mpl_prep(const float* __restrict__ w, const void* __restrict__ abits) {
    int i = blockIdx.x * 256 + threadIdx.x;
    if (i < LEVELS * DOUT * DIN)
        g_w[i] = __float2half_rn(w[i]);
    if (blockIdx.x == 0 && threadIdx.x == 0) {
        const long long* p64 = (const long long*)abits;
        const int* p32 = (const int*)abits;
        bool is64 = true;
        #pragma unroll
        for (int p = 0; p < PN; p++) {
            long long v = p64[p];
            if (v < 0 || v >= LEVELS) is64 = false;
        }
        #pragma unroll
        for (int p = 0; p < PN; p++) {
            int lv = is64 ? (int)p64[p] : p32[p];
            if (lv < 0) lv = 0;
            if (lv >= LEVELS) lv = LEVELS - 1;
            g_levels[p] = lv;
        }
    }
}

// ---------------- main GEMM kernel ----------------
__global__ void __launch_bounds__(NTHREADS, 1)
mpl_kernel(const float* __restrict__ x, const float* __restrict__ bias,
           float* __restrict__ out)
{
    extern __shared__ char smem[];
    const uint32_t sb = smem_u32(smem);
    const int tid = threadIdx.x;
    const int wid = tid >> 5;
    const int lid = tid & 31;
    const int m0 = blockIdx.x * TILE_M;
    const int path = m0 / M_PER_PATH;
    const int level = g_levels[path];

    const float* xbase = x + (size_t)m0 * DIN;
    const __half* wb = g_w + (size_t)level * DOUT * DIN;

    // warp tile: 64(M) x 64(N); warp grid 2(M) x 4(N)
    const int mrow0 = (wid >> 2) * 64;
    const int ncol0 = (wid & 3) * 64;

    // per-lane ldmatrix address components
    const int g = lid >> 3;           // matrix group 0..3
    const int lr = lid & 7;           // row within matrix
    const int a_row = (g & 1) * 8 + lr;   // A: m,(m+8),m,(m+8)
    const int a_kb  = (g >> 1) * 16;      //    k,  k,  k+8, k+8 (bytes)
    const int b_row = (g >> 1) * 8 + lr;  // B: n,  n,  n+8, n+8
    const int b_kb  = (g & 1) * 16;       //    k, k+8,  k,  k+8 (bytes)

    float4 av[8];
    // ---------- prologue: fill buffer 0 with chunk 0 ----------
    {
        #pragma unroll
        for (int i = 0; i < 8; i++) {
            int idx = tid + i * NTHREADS;
            int r = idx >> 4, cg = idx & 15;
            av[i] = *(const float4*)(xbase + (size_t)r * DIN + cg * 4);
        }
        #pragma unroll
        for (int i = 0; i < 8; i++) {
            int idx = tid + i * NTHREADS;
            int n = idx >> 3, c8 = idx & 7;
            uint32_t sw = SWZ((uint32_t)(n * 128 + c8 * 16));
            cp16(sb + B_OFF + sw, wb + (size_t)n * DIN + c8 * 8);
        }
        CP_COMMIT();
        #pragma unroll
        for (int i = 0; i < 8; i++) {
            int idx = tid + i * NTHREADS;
            int r = idx >> 4, cg = idx & 15;
            uint32_t sw = SWZ((uint32_t)(r * 128 + cg * 8));
            *(uint2*)(smem + A_OFF + sw) =
                make_uint2(pack_h2(av[i].x, av[i].y), pack_h2(av[i].z, av[i].w));
        }
        CP_WAIT0();
        __syncthreads();
    }

    float acc[4][8][4];
    #pragma unroll
    for (int mt = 0; mt < 4; mt++)
        #pragma unroll
        for (int nt = 0; nt < 8; nt++)
            #pragma unroll
            for (int e = 0; e < 4; e++) acc[mt][nt][e] = 0.0f;

    // ---------- main loop over K chunks ----------
    #pragma unroll
    for (int kc = 0; kc < NCHUNK; kc++) {
        const uint32_t bufb = sb + (kc & 1) * BUF_BYTES;
        const uint32_t nbufb = sb + ((kc + 1) & 1) * BUF_BYTES;

        // prefetch next chunk: cp.async B, LDG A into regs (overlap with compute)
        if (kc < NCHUNK - 1) {
            const int kn = kc + 1;
            #pragma unroll
            for (int i = 0; i < 8; i++) {
                int idx = tid + i * NTHREADS;
                int n = idx >> 3, c8 = idx & 7;
                uint32_t sw = SWZ((uint32_t)(n * 128 + c8 * 16));
                cp16(nbufb + B_OFF + sw, wb + (size_t)n * DIN + kn * KCH + c8 * 8);
            }
            CP_COMMIT();
            #pragma unroll
            for (int i = 0; i < 8; i++) {
                int idx = tid + i * NTHREADS;
                int r = idx >> 4, cg = idx & 15;
                av[i] = *(const float4*)(xbase + (size_t)r * DIN + kn * KCH + cg * 4);
            }
        }

        // ---- compute current chunk: 4 k-steps ----
        const uint32_t abase = bufb + A_OFF;
        const uint32_t bbase = bufb + B_OFF;
        #pragma unroll
        for (int ks = 0; ks < 4; ks++) {
            uint32_t af[4][4];
            #pragma unroll
            for (int mt = 0; mt < 4; mt++) {
                uint32_t byte = (uint32_t)((mrow0 + mt * 16 + a_row) * 128 + ks * 32 + a_kb);
                ldsm4(af[mt], abase + SWZ(byte));
            }
            uint32_t bf[4][4];
            #pragma unroll
            for (int p = 0; p < 4; p++) {
                uint32_t byte = (uint32_t)((ncol0 + p * 16 + b_row) * 128 + ks * 32 + b_kb);
                ldsm4(bf[p], bbase + SWZ(byte));
            }
            #pragma unroll
            for (int mt = 0; mt < 4; mt++)
                #pragma unroll
                for (int p = 0; p < 4; p++) {
                    mma16816(acc[mt][2 * p + 0], af[mt], &bf[p][0]);
                    mma16816(acc[mt][2 * p + 1], af[mt], &bf[p][2]);
                }
        }

        // ---- stage next chunk's A; close pipeline stage ----
        if (kc < NCHUNK - 1) {
            #pragma unroll
            for (int i = 0; i < 8; i++) {
                int idx = tid + i * NTHREADS;
                int r = idx >> 4, cg = idx & 15;
                uint32_t sw = SWZ((uint32_t)(r * 128 + cg * 8));
                *(uint2*)(smem + ((kc + 1) & 1) * BUF_BYTES + A_OFF + sw) =
                    make_uint2(pack_h2(av[i].x, av[i].y), pack_h2(av[i].z, av[i].w));
            }
            CP_WAIT0();
            __syncthreads();
        }
    }

    // ---------- epilogue: bias + direct coalesced stores ----------
    const int qrow = lid >> 2;            // 0..7
    const int qcol = (lid & 3) * 2;       // 0,2,4,6
    float2 bv[8];
    #pragma unroll
    for (int nt = 0; nt < 8; nt++)
        bv[nt] = *(const float2*)(bias + ncol0 + nt * 8 + qcol);

    float* op = out + (size_t)m0 * DOUT;
    #pragma unroll
    for (int mt = 0; mt < 4; mt++) {
        int r0 = mrow0 + mt * 16 + qrow;
        #pragma unroll
        for (int nt = 0; nt < 8; nt++) {
            int c = ncol0 + nt * 8 + qcol;
            float2 v0, v1;
            v0.x = acc[mt][nt][0] + bv[nt].x;
            v0.y = acc[mt][nt][1] + bv[nt].y;
            v1.x = acc[mt][nt][2] + bv[nt].x;
            v1.y = acc[mt][nt][3] + bv[nt].y;
            *(float2*)(op + (size_t)r0 * DOUT + c) = v0;
            *(float2*)(op + (size_t)(r0 + 8) * DOUT + c) = v1;
        }
    }
}

// ---------------- launch: identify inputs BY ELEMENT COUNT (order-proof) ----------------
extern "C" void kernel_launch(void* const* d_in, const int* in_sizes, int n_in,
                              void* d_out, int out_size) {
    const float* x = nullptr;
    const float* weight_bank = nullptr;
    const float* bias = nullptr;
    const void* abits = nullptr;

    for (int i = 0; i < n_in; i++) {
        int s = in_sizes[i];
        if (s == M_TOTAL * DIN)             x = (const float*)d_in[i];           // 67108864
        else if (s == LEVELS * DOUT * DIN)  weight_bank = (const float*)d_in[i]; // 458752
        else if (s == DOUT)                 bias = (const float*)d_in[i];        // 256
        else if (s == PN)                   abits = d_in[i];                     // 8
    }

    float* out = (float*)d_out;

    cudaFuncSetAttribute(mpl_kernel, cudaFuncAttributeMaxDynamicSharedMemorySize, SMEM_BYTES);

    mpl_prep<<<(LEVELS * DOUT * DIN + 255) / 256, 256>>>(weight_bank, abits);
    mpl_kernel<<<GRID, NTHREADS, SMEM_BYTES>>>(x, bias, out);
}